// round 12
// baseline (speedup 1.0000x reference)
#include <cuda_runtime.h>
#include <cstdint>
#include <math.h>

#define BB   64
#define HH   128
#define NT   4096
#define EE   131072
#define KK   52
#define NK   3328
#define NEG  0.01f

// Global scratch: folded W1 (4 heads x 384 x 256):
// rows 0..127 = W1_0+W1_2, 128..255 = W1_1-W1_2, 256..383 = W1_3
__device__ float g_wf[4*384*256];

// ---------------- shared memory layout (float offsets) — 171 KB total ------
#define SM_M    0          // 4096  M[c*64+r] = A_d[r][c]
#define SM_S    4096       // 4096  S[r*64+c]
#define SM_X    8192       // 8192  x -> xc (overwritten)
#define SM_Q    16384      // 8192  q (xq / qt / xq2)
#define SM_A    24576      // 8192  hop-tmp / a / agg / A2-T
#define SM_H    32768      // 8192  h1half / h2
#define SM_MISC 40960
#define MS_DEG   0
#define MS_DINV  64
#define MS_FOWN  128
#define MS_FPEER 192
#define MS_GOWN  256
#define MS_GPEER 320
#define MS_SCORE 384
#define MS_RED   448       // 256 floats
#define MS_PERM  704       // 64 ints
#define MS_CNT   768       // 2048 ints (packed 2x uint16)
#define SM_TOTALF (SM_MISC + 768 + 2048)
#define SM_BYTES  (SM_TOTALF * 4)

#define NTHR 256

__device__ __forceinline__ float leaky(float v) { return v > 0.0f ? v : NEG * v; }

// ---- packed fp32 (f32x2) ----
__device__ __forceinline__ unsigned long long packf2(float f) {
    unsigned long long d; unsigned int u = __float_as_uint(f);
    asm("mov.b64 %0, {%1, %1};" : "=l"(d) : "r"(u));
    return d;
}
__device__ __forceinline__ void fma2(unsigned long long& acc,
                                     unsigned long long a, unsigned long long b) {
    asm("fma.rn.f32x2 %0, %1, %2, %0;" : "+l"(acc) : "l"(a), "l"(b));
}
__device__ __forceinline__ unsigned long long mul2(unsigned long long a,
                                                   unsigned long long b) {
    unsigned long long o;
    asm("mul.rn.f32x2 %0, %1, %2;" : "=l"(o) : "l"(a), "l"(b));
    return o;
}
__device__ __forceinline__ void unpackf2(unsigned long long v, float& lo, float& hi) {
    unsigned int ul, uh;
    asm("mov.b64 {%0, %1}, %2;" : "=r"(ul), "=r"(uh) : "l"(v));
    lo = __uint_as_float(ul); hi = __uint_as_float(uh);
}

// ---- cluster helpers ----
__device__ __forceinline__ void cluster_sync() {
    asm volatile("barrier.cluster.arrive.aligned;" ::: "memory");
    asm volatile("barrier.cluster.wait.aligned;" ::: "memory");
}
__device__ __forceinline__ float dsread(const float* p, unsigned peer) {
    unsigned addr = (unsigned)__cvta_generic_to_shared((void*)p);
    unsigned ra; float v;
    asm volatile("mapa.shared::cluster.u32 %0, %1, %2;" : "=r"(ra) : "r"(addr), "r"(peer));
    asm volatile("ld.shared::cluster.f32 %0, [%1];" : "=f"(v) : "r"(ra));
    return v;
}

// ---- GEMM microkernel: C[64 x 128], tile 4 rows x 8 cols (4 f32x2 pairs) --
// ty = t>>4 (16 row groups), txc = t&15 (16 col groups of 8).
// True ping-pong 2-chunk pipeline: A and W for the next 4-k chunk load while
// the current chunk computes; no register copy-MOVs.
template<int K>
__device__ __forceinline__ void gseg(const float* __restrict__ As, int ldA,
                                     const float* __restrict__ W, int wld,
                                     int ty, int txc, unsigned long long acc[4][4]) {
    const float* a0 = As + ty * 4 * ldA;
    const float* wbase = W + txc * 8;
    ulonglong2 w0[4][2], w1[4][2];
    float4 av0[4], av1[4];
    #pragma unroll
    for (int kk = 0; kk < 4; kk++) {
        w0[kk][0] = *(const ulonglong2*)(wbase + (size_t)kk * wld);
        w0[kk][1] = *(const ulonglong2*)(wbase + (size_t)kk * wld + 4);
    }
    #pragma unroll
    for (int r = 0; r < 4; r++) av0[r] = *(const float4*)(a0 + r * ldA);
    #pragma unroll 1
    for (int k = 0; k < K; k += 8) {
        // prefetch chunk k+4 (always exists: K % 8 == 0)
        #pragma unroll
        for (int kk = 0; kk < 4; kk++) {
            w1[kk][0] = *(const ulonglong2*)(wbase + (size_t)(k + 4 + kk) * wld);
            w1[kk][1] = *(const ulonglong2*)(wbase + (size_t)(k + 4 + kk) * wld + 4);
        }
        #pragma unroll
        for (int r = 0; r < 4; r++) av1[r] = *(const float4*)(a0 + r * ldA + k + 4);
        // compute chunk k with (av0, w0)
        #pragma unroll
        for (int kk = 0; kk < 4; kk++) {
            #pragma unroll
            for (int r = 0; r < 4; r++) {
                float aval = kk == 0 ? av0[r].x : kk == 1 ? av0[r].y
                           : kk == 2 ? av0[r].z : av0[r].w;
                unsigned long long a2 = packf2(aval);
                fma2(acc[r][0], a2, w0[kk][0].x);
                fma2(acc[r][1], a2, w0[kk][0].y);
                fma2(acc[r][2], a2, w0[kk][1].x);
                fma2(acc[r][3], a2, w0[kk][1].y);
            }
        }
        // prefetch chunk k+8 into stage 0
        if (k + 8 < K) {
            #pragma unroll
            for (int kk = 0; kk < 4; kk++) {
                w0[kk][0] = *(const ulonglong2*)(wbase + (size_t)(k + 8 + kk) * wld);
                w0[kk][1] = *(const ulonglong2*)(wbase + (size_t)(k + 8 + kk) * wld + 4);
            }
            #pragma unroll
            for (int r = 0; r < 4; r++) av0[r] = *(const float4*)(a0 + r * ldA + k + 8);
        }
        // compute chunk k+4 with (av1, w1)
        #pragma unroll
        for (int kk = 0; kk < 4; kk++) {
            #pragma unroll
            for (int r = 0; r < 4; r++) {
                float aval = kk == 0 ? av1[r].x : kk == 1 ? av1[r].y
                           : kk == 2 ? av1[r].z : av1[r].w;
                unsigned long long a2 = packf2(aval);
                fma2(acc[r][0], a2, w1[kk][0].x);
                fma2(acc[r][1], a2, w1[kk][0].y);
                fma2(acc[r][2], a2, w1[kk][1].x);
                fma2(acc[r][3], a2, w1[kk][1].y);
            }
        }
    }
}

// Fused h1 microkernel: acc += a@Wf0 + q@Wf1 + (a*q)@Wf2, K=128, half cols.
// Tile 4 rows x 8 cols; W streams prefetched one 2-k chunk ahead (copy style).
__device__ __forceinline__ void gsegH1(const float* __restrict__ a,
                                       const float* __restrict__ q,
                                       const float* __restrict__ Wf, int half,
                                       int ty, int txc, unsigned long long acc[4][4]) {
    const float* a0 = a + ty * 4 * 128;
    const float* q0 = q + ty * 4 * 128;
    const float* w0 = Wf + half * 128 + txc * 8;
    ulonglong2 wa[2][2], wq[2][2], wm[2][2];
    #pragma unroll
    for (int kk = 0; kk < 2; kk++) {
        wa[kk][0] = *(const ulonglong2*)(w0 + (size_t)kk * 256);
        wa[kk][1] = *(const ulonglong2*)(w0 + (size_t)kk * 256 + 4);
        wq[kk][0] = *(const ulonglong2*)(w0 + (size_t)(128 + kk) * 256);
        wq[kk][1] = *(const ulonglong2*)(w0 + (size_t)(128 + kk) * 256 + 4);
        wm[kk][0] = *(const ulonglong2*)(w0 + (size_t)(256 + kk) * 256);
        wm[kk][1] = *(const ulonglong2*)(w0 + (size_t)(256 + kk) * 256 + 4);
    }
    #pragma unroll 2
    for (int k = 0; k < 128; k += 2) {
        ulonglong2 na[2][2], nq[2][2], nm[2][2];
        if (k + 2 < 128) {
            #pragma unroll
            for (int kk = 0; kk < 2; kk++) {
                na[kk][0] = *(const ulonglong2*)(w0 + (size_t)(k + 2 + kk) * 256);
                na[kk][1] = *(const ulonglong2*)(w0 + (size_t)(k + 2 + kk) * 256 + 4);
                nq[kk][0] = *(const ulonglong2*)(w0 + (size_t)(128 + k + 2 + kk) * 256);
                nq[kk][1] = *(const ulonglong2*)(w0 + (size_t)(128 + k + 2 + kk) * 256 + 4);
                nm[kk][0] = *(const ulonglong2*)(w0 + (size_t)(256 + k + 2 + kk) * 256);
                nm[kk][1] = *(const ulonglong2*)(w0 + (size_t)(256 + k + 2 + kk) * 256 + 4);
            }
        }
        float2 av[4], qv[4];
        #pragma unroll
        for (int r = 0; r < 4; r++) {
            av[r] = *(const float2*)(a0 + r * 128 + k);
            qv[r] = *(const float2*)(q0 + r * 128 + k);
        }
        #pragma unroll
        for (int kk = 0; kk < 2; kk++) {
            #pragma unroll
            for (int r = 0; r < 4; r++) {
                float aval = kk ? av[r].y : av[r].x;
                float qval = kk ? qv[r].y : qv[r].x;
                unsigned long long a2 = packf2(aval);
                unsigned long long q2 = packf2(qval);
                unsigned long long m2 = mul2(a2, q2);
                fma2(acc[r][0], a2, wa[kk][0].x); fma2(acc[r][1], a2, wa[kk][0].y);
                fma2(acc[r][2], a2, wa[kk][1].x); fma2(acc[r][3], a2, wa[kk][1].y);
                fma2(acc[r][0], q2, wq[kk][0].x); fma2(acc[r][1], q2, wq[kk][0].y);
                fma2(acc[r][2], q2, wq[kk][1].x); fma2(acc[r][3], q2, wq[kk][1].y);
                fma2(acc[r][0], m2, wm[kk][0].x); fma2(acc[r][1], m2, wm[kk][0].y);
                fma2(acc[r][2], m2, wm[kk][1].x); fma2(acc[r][3], m2, wm[kk][1].y);
            }
        }
        #pragma unroll
        for (int kk = 0; kk < 2; kk++) {
            wa[kk][0] = na[kk][0]; wa[kk][1] = na[kk][1];
            wq[kk][0] = nq[kk][0]; wq[kk][1] = nq[kk][1];
            wm[kk][0] = nm[kk][0]; wm[kk][1] = nm[kk][1];
        }
    }
}

// Transposed-A variant for agg: A[c][k] = S[k*64+c], tile 4 rows x 8 cols
__device__ __forceinline__ void gsegT(const float* __restrict__ S,
                                      const float* __restrict__ W, int wld, int K,
                                      int ty, int txc, unsigned long long acc[4][4]) {
    int c0 = ty * 4;
    const float* wbase = W + txc * 8;
    for (int k = 0; k < K; k++) {
        const ulonglong2 p0 = *(const ulonglong2*)(wbase + (size_t)k * wld);
        const ulonglong2 p1 = *(const ulonglong2*)(wbase + (size_t)k * wld + 4);
        #pragma unroll
        for (int r = 0; r < 4; r++) {
            unsigned long long a2 = packf2(S[k * 64 + c0 + r]);
            fma2(acc[r][0], a2, p0.x);
            fma2(acc[r][1], a2, p0.y);
            fma2(acc[r][2], a2, p1.x);
            fma2(acc[r][3], a2, p1.y);
        }
    }
}

template<int ACT>
__device__ __forceinline__ void estore(float* C, int ldC, int ty, int txc,
                                       unsigned long long acc[4][4]) {
    #pragma unroll
    for (int r = 0; r < 4; r++) {
        float* crow = C + (ty * 4 + r) * ldC + txc * 8;
        #pragma unroll
        for (int j = 0; j < 4; j++) {
            float lo, hi; unpackf2(acc[r][j], lo, hi);
            if (ACT == 1) { lo = leaky(lo); hi = leaky(hi); }
            ((float2*)crow)[j] = make_float2(lo, hi);
        }
    }
}

// ---- in-place softmax over v[0..63] ----
__device__ void softmax64(float* v, float* red, int t) {
    if (t < 64) red[t] = v[t];
    __syncthreads();
    for (int o = 32; o; o >>= 1) { if (t < o) red[t] = fmaxf(red[t], red[t + o]); __syncthreads(); }
    float m = red[0];
    __syncthreads();
    if (t < 64) { float e = expf(v[t] - m); v[t] = e; red[t] = e; }
    __syncthreads();
    for (int o = 32; o; o >>= 1) { if (t < o) red[t] += red[t + o]; __syncthreads(); }
    float d = red[0];
    __syncthreads();
    if (t < 64) v[t] = v[t] / d;
    __syncthreads();
}

// ---- attention branch: fout = segsoftmax(leaky(MLP(kv, q))) ---------------
__device__ void attention(float* sm, int t, int ty, int txc,
                          const float* kv, const float* q,
                          int head, const float* Wk, const float* W2,
                          const float* W3, float* fout) {
    float* red = sm + SM_MISC + MS_RED;
    float* Ab  = sm + SM_A;
    float* Hb  = sm + SM_H;

    // a = kv @ Wk[head]
    {
        unsigned long long acc[4][4];
        #pragma unroll
        for (int r = 0; r < 4; r++)
            #pragma unroll
            for (int j = 0; j < 4; j++) acc[r][j] = 0ull;
        gseg<128>(kv, 128, Wk + head * 16384, 128, ty, txc, acc);
        estore<0>(Ab, 128, ty, txc, acc);
    }
    __syncthreads();

    // h2 accumulated across two h1 halves
    unsigned long long h2acc[4][4];
    #pragma unroll
    for (int r = 0; r < 4; r++)
        #pragma unroll
        for (int j = 0; j < 4; j++) h2acc[r][j] = 0ull;
    const float* Wf = g_wf + (size_t)head * 384 * 256;
    #pragma unroll 1
    for (int half = 0; half < 2; half++) {
        unsigned long long acc[4][4];
        #pragma unroll
        for (int r = 0; r < 4; r++)
            #pragma unroll
            for (int j = 0; j < 4; j++) acc[r][j] = 0ull;
        gsegH1(Ab, q, Wf, half, ty, txc, acc);
        estore<1>(Hb, 128, ty, txc, acc);   // h1half (leaky)
        __syncthreads();
        gseg<128>(Hb, 128, W2 + head * 32768 + half * 16384, 128, ty, txc, h2acc);
        __syncthreads();                     // protect Hb before next overwrite
    }
    estore<1>(Hb, 128, ty, txc, h2acc);      // h2 (leaky)
    __syncthreads();

    // logit = leaky(h2 @ W3[head]); segment softmax over 64
    {
        int row = t >> 2, part = t & 3;
        const float4* hp = (const float4*)(Hb + row * 128 + part * 32);
        const float4* wp = (const float4*)(W3 + head * 128 + part * 32);
        float s = 0.0f;
        #pragma unroll
        for (int i = 0; i < 8; i++) {
            float4 a = hp[i], b = wp[i];
            s += a.x * b.x + a.y * b.y + a.z * b.z + a.w * b.w;
        }
        red[t] = s;
    }
    __syncthreads();
    if (t < 64) fout[t] = leaky(red[t * 4] + red[t * 4 + 1] + red[t * 4 + 2] + red[t * 4 + 3]);
    __syncthreads();
    softmax64(fout, red, t);
}

// ---------------- fold W1 ----------------
__global__ void fold_k(const float* __restrict__ W1) {
    int i = blockIdx.x * 256 + threadIdx.x;
    if (i >= 4 * 384 * 256) return;
    int w = i / (384 * 256);
    int rem = i - w * (384 * 256);
    int r = rem >> 8, c = rem & 255;
    const float* base = W1 + (size_t)w * 512 * 256;
    float v;
    if (r < 128)      v = base[r * 256 + c] + base[(r + 256) * 256 + c];
    else if (r < 256) v = base[r * 256 + c] - base[(r + 128) * 256 + c];
    else              v = base[(r + 128) * 256 + c];
    g_wf[i] = v;
}

// ---------------- THE mega kernel: one 2-CTA cluster = one batch -----------
extern __shared__ float sm[];

__global__ void __launch_bounds__(NTHR, 1) __cluster_dims__(2, 1, 1)
mega_k(const float* __restrict__ xg, const int* __restrict__ ei,
       const float* __restrict__ ew, const float* __restrict__ tx,
       const float* __restrict__ Wk, const float* __restrict__ W2,
       const float* __restrict__ W3, const float* __restrict__ lW,
       float* __restrict__ outx, float* __restrict__ outA2,
       float* __restrict__ outb, float* __restrict__ outp) {
    int t = threadIdx.x;
    int ty = t >> 4, txc = t & 15;    // 4-row x 8-col thread tile
    int b = blockIdx.x >> 1;
    unsigned rank = blockIdx.x & 1;

    float* Ms    = sm + SM_M;
    float* Ss    = sm + SM_S;
    float* xs    = sm + SM_X;       // x, later xc
    float* qs    = sm + SM_Q;
    float* Ab    = sm + SM_A;
    float* degs  = sm + SM_MISC + MS_DEG;
    float* dinvs = sm + SM_MISC + MS_DINV;
    float* fown  = sm + SM_MISC + MS_FOWN;
    float* fpeer = sm + SM_MISC + MS_FPEER;
    float* gown  = sm + SM_MISC + MS_GOWN;
    float* gpeer = sm + SM_MISC + MS_GPEER;
    float* sscore= sm + SM_MISC + MS_SCORE;
    float* red   = sm + SM_MISC + MS_RED;
    int*   permsh= (int*)(sm + SM_MISC + MS_PERM);
    int*   cw    = (int*)(sm + SM_MISC + MS_CNT);

    // ---- zero this CTA's A2 row-strip (26 rows x NK), overlapped ----
    {
        float4 z = make_float4(0.0f, 0.0f, 0.0f, 0.0f);
        float4* dst = (float4*)(outA2 + ((size_t)b * KK + rank * 26) * NK);
        for (int i = t; i < 26 * NK / 4; i += NTHR) dst[i] = z;
    }

    // ---- stage 0: load x, init, build deg/dinv/M/Cnt ----
    for (int i = t; i < 4096; i += NTHR) Ms[i] = 0.0f;
    for (int i = t; i < 2048; i += NTHR) cw[i] = 0;
    if (t < 64) degs[t] = 1.0f;
    for (int i = t * 4; i < 8192; i += NTHR * 4)
        *(float4*)(xs + i) = *(const float4*)(xg + (size_t)b * 8192 + i);
    __syncthreads();

    int er[8], ec[8]; float ewv[8];
    #pragma unroll
    for (int u = 0; u < 8; u++) {
        int e = b * 2048 + t + u * NTHR;
        er[u] = ei[e] - b * 64;
        ec[u] = ei[EE + e] - b * 64;
        ewv[u] = ew[e];
        atomicAdd(&degs[ec[u]], ewv[u]);
    }
    __syncthreads();
    if (t < 64) {
        float d = degs[t];
        dinvs[t] = d > 0.0f ? (1.0f / sqrtf(fmaxf(d, 1e-12f))) : 0.0f;
    }
    __syncthreads();
    #pragma unroll
    for (int u = 0; u < 8; u++) {
        atomicAdd(&Ms[ec[u] * 64 + er[u]], dinvs[er[u]] * ewv[u] * dinvs[ec[u]]);
        atomicAdd(&cw[(er[u] * 64 + ec[u]) >> 1], 1 << ((ec[u] & 1) * 16));
    }
    if (t < 64) {
        float dv = dinvs[t];
        atomicAdd(&Ms[t * 64 + t], dv * dv);
        atomicAdd(&cw[(t * 64 + t) >> 1], 1 << ((t & 1) * 16));
    }
    __syncthreads();

    // ---- stage 1: q = hop2(x) for rank0; q = broadcast target for rank1 ----
    if (rank == 0) {
        unsigned long long acc[4][4];
        #pragma unroll
        for (int r = 0; r < 4; r++)
            #pragma unroll
            for (int j = 0; j < 4; j++) acc[r][j] = 0ull;
        gseg<64>(Ms, 64, xs, 128, ty, txc, acc);
        estore<0>(Ab, 128, ty, txc, acc);
        __syncthreads();
        unsigned long long acc2[4][4];
        #pragma unroll
        for (int r = 0; r < 4; r++)
            #pragma unroll
            for (int j = 0; j < 4; j++) acc2[r][j] = 0ull;
        gseg<64>(Ms, 64, Ab, 128, ty, txc, acc2);
        estore<0>(qs, 128, ty, txc, acc2);
    } else {
        for (int i = t * 4; i < 8192; i += NTHR * 4)
            *(float4*)(qs + i) = *(const float4*)(tx + b * 128 + (i & 127));
    }
    __syncthreads();

    // ---- stage 2: attention #1 (head = rank) -> fown ----
    attention(sm, t, ty, txc, xs, qs, (int)rank, Wk, W2, W3, fown);

    cluster_sync();
    if (t < 64) fpeer[t] = dsread(fown + t, rank ^ 1);
    __syncthreads();

    // ---- stage 3: build S (edge softmax, count-weighted) ----
    {
        const float* f1 = rank ? fpeer : fown;
        const float* f2 = rank ? fown : fpeer;
        int c = t >> 2, rq = t & 3;
        float f1c = f1[c];
        float mx = -3.0e38f;
        for (int r = rq * 16; r < rq * 16 + 16; r++) {
            int cnt = (cw[(r * 64 + c) >> 1] >> ((c & 1) * 16)) & 0xffff;
            if (cnt) mx = fmaxf(mx, leaky(f1c + f2[r]));
        }
        red[t] = mx; __syncthreads();
        mx = fmaxf(fmaxf(red[c * 4], red[c * 4 + 1]), fmaxf(red[c * 4 + 2], red[c * 4 + 3]));
        __syncthreads();
        float dp = 0.0f;
        for (int r = rq * 16; r < rq * 16 + 16; r++) {
            int cnt = (cw[(r * 64 + c) >> 1] >> ((c & 1) * 16)) & 0xffff;
            float e = 0.0f;
            if (cnt) e = (float)cnt * expf(leaky(f1c + f2[r]) - mx);
            Ss[r * 64 + c] = e; dp += e;
        }
        red[t] = dp; __syncthreads();
        float inv = 1.0f / (red[c * 4] + red[c * 4 + 1] + red[c * 4 + 2] + red[c * 4 + 3]);
        for (int r = rq * 16; r < rq * 16 + 16; r++) Ss[r * 64 + c] *= inv;
        __syncthreads();
    }

    // ---- stage 4: agg = S^T x -> Ab ; xc = mean_h leaky(x + agg @ lW[h]) ----
    {
        unsigned long long acc[4][4];
        #pragma unroll
        for (int r = 0; r < 4; r++)
            #pragma unroll
            for (int j = 0; j < 4; j++) acc[r][j] = 0ull;
        gsegT(Ss, xs, 128, 64, ty, txc, acc);
        estore<0>(Ab, 128, ty, txc, acc);
    }
    __syncthreads();
    {
        unsigned long long a0[4][4], a1[4][4];
        #pragma unroll
        for (int r = 0; r < 4; r++)
            #pragma unroll
            for (int j = 0; j < 4; j++) { a0[r][j] = 0ull; a1[r][j] = 0ull; }
        gseg<128>(Ab, 128, lW,         128, ty, txc, a0);
        gseg<128>(Ab, 128, lW + 16384, 128, ty, txc, a1);
        #pragma unroll
        for (int r = 0; r < 4; r++) {
            int row = ty * 4 + r;
            #pragma unroll
            for (int j = 0; j < 4; j++) {
                float l0, h0, l1, h1v;
                unpackf2(a0[r][j], l0, h0);
                unpackf2(a1[r][j], l1, h1v);
                int col = txc * 8 + 2 * j;
                float x0 = xs[row * 128 + col], x1 = xs[row * 128 + col + 1];
                float vlo = 0.5f * (leaky(x0 + l0) + leaky(x0 + l1));
                float vhi = 0.5f * (leaky(x1 + h0) + leaky(x1 + h1v));
                *(float2*)(xs + row * 128 + col) = make_float2(vlo, vhi);  // x -> xc in place
            }
        }
    }
    __syncthreads();

    // ---- stage 5: q2 = hop2(xc) for rank0 (rank1 keeps qt in qs) ----
    if (rank == 0) {
        unsigned long long acc[4][4];
        #pragma unroll
        for (int r = 0; r < 4; r++)
            #pragma unroll
            for (int j = 0; j < 4; j++) acc[r][j] = 0ull;
        gseg<64>(Ms, 64, xs, 128, ty, txc, acc);
        estore<0>(Ab, 128, ty, txc, acc);
        __syncthreads();
        unsigned long long acc2[4][4];
        #pragma unroll
        for (int r = 0; r < 4; r++)
            #pragma unroll
            for (int j = 0; j < 4; j++) acc2[r][j] = 0ull;
        gseg<64>(Ms, 64, Ab, 128, ty, txc, acc2);
        estore<0>(qs, 128, ty, txc, acc2);
        __syncthreads();
    }

    // ---- stage 6: attention #2 (head = 2 + rank), kv = xc -> gown ----
    attention(sm, t, ty, txc, xs, qs, 2 + (int)rank, Wk, W2, W3, gown);

    cluster_sync();
    if (t < 64) gpeer[t] = dsread(gown + t, rank ^ 1);
    __syncthreads();

    // ---- stage 7: cluster score softmax + top-52 ----
    if (t < 64) sscore[t] = gown[t] + gpeer[t];
    __syncthreads();
    softmax64(sscore, red, t);
    if (t < 32) {
        float v0 = sscore[t], v1 = sscore[t + 32];
        for (int j = 0; j < KK; j++) {
            float mv = v0; int mi = t;
            if (v1 > mv) { mv = v1; mi = t + 32; }
            #pragma unroll
            for (int off = 16; off; off >>= 1) {
                float ov = __shfl_xor_sync(0xffffffffu, mv, off);
                int   oi = __shfl_xor_sync(0xffffffffu, mi, off);
                if (ov > mv || (ov == mv && oi < mi)) { mv = ov; mi = oi; }
            }
            if (t == 0) permsh[j] = mi;
            if (mi < 32) { if (t == mi) v0 = -3.0e38f; }
            else         { if (t == mi - 32) v1 = -3.0e38f; }
        }
    }
    __syncthreads();

    // ---- stage 8: outputs ----
    if (rank == 0) {
        // x_out: re-read x from global (xs now holds xc)
        for (int i = t; i < KK * 32; i += NTHR) {
            int e = i >> 5, c4 = (i & 31) * 4;
            int p = permsh[e];
            float sc = sscore[p];
            float4 xv = *(const float4*)(xg + (size_t)b * 8192 + p * 128 + c4);
            *(float4*)(outx + (size_t)(b * KK + e) * 128 + c4) =
                make_float4(xv.x * sc, xv.y * sc, xv.z * sc, xv.w * sc);
        }
        if (t < KK) {
            int p = permsh[t];
            outb[b * KK + t] = (float)b;
            outp[b * KK + t] = (float)(b * 64 + p);
        }
    }

    // A2 block: T = A_d @ S_sel (in Ab); A2 rows split by rank
    float* T = Ab;   // 64*52 floats
    __syncthreads();
    for (int i = t; i < 64 * KK; i += NTHR) {
        int r = i / KK, j = i - r * KK;
        int cj = permsh[j];
        float acc = 0.0f;
        #pragma unroll
        for (int c = 0; c < 64; c++) acc += Ms[c * 64 + r] * Ss[c * 64 + cj];
        T[i] = acc;
    }
    __syncthreads();
    for (int o = t; o < 26 * KK; o += NTHR) {
        int il = o / KK, j = o - il * KK;
        int i = (int)rank * 26 + il;
        float v;
        if (i == j) v = 1.0f;
        else {
            int ci = permsh[i];
            v = 0.0f;
            #pragma unroll
            for (int r = 0; r < 64; r++) v += Ss[r * 64 + ci] * T[r * KK + j];
        }
        outA2[(size_t)(b * KK + i) * NK + (size_t)(b * KK + j)] = v;
    }
}

// =======================================================================
extern "C" void kernel_launch(void* const* d_in, const int* in_sizes, int n_in,
                              void* d_out, int out_size) {
    const float* x   = (const float*)d_in[0];
    const int*   ei  = (const int*)d_in[1];
    const float* ewt = (const float*)d_in[2];
    const float* tx  = (const float*)d_in[3];
    const float* Wk  = (const float*)d_in[5];
    const float* W1  = (const float*)d_in[6];
    const float* W2  = (const float*)d_in[7];
    const float* W3  = (const float*)d_in[8];
    const float* lW  = (const float*)d_in[9];
    float* out = (float*)d_out;

    float* out_x    = out;
    float* out_A2   = out + (size_t)NK * HH;
    float* out_bat  = out + (size_t)NK * HH + (size_t)NK * NK;
    float* out_perm = out_bat + NK;

    cudaFuncSetAttribute(mega_k, cudaFuncAttributeMaxDynamicSharedMemorySize, SM_BYTES);

    fold_k<<<(4 * 384 * 256 + 255) / 256, 256>>>(W1);
    mega_k<<<2 * BB, NTHR, SM_BYTES>>>(x, ei, ewt, tx, Wk, W2, W3, lW,
                                       out_x, out_A2, out_bat, out_perm);
}

// round 14
// speedup vs baseline: 1.2623x; 1.2623x over previous
#include <cuda_runtime.h>
#include <cstdint>
#include <math.h>

#define BB   64
#define HH   128
#define NT   4096
#define EE   131072
#define KK   52
#define NK   3328
#define NEG  0.01f

// Global scratch: folded W1 (4 heads x 384 x 256):
// rows 0..127 = W1_0+W1_2, 128..255 = W1_1-W1_2, 256..383 = W1_3
__device__ float g_wf[4*384*256];

// ---------------- shared memory layout (float offsets) — ~172 KB ----------
#define SM_M    0          // 4096  M[c*64+r] = A_d[r][c]
#define SM_S    4096       // 4096  S[r*64+c]
#define SM_X    8192       // 8192  x -> xc (overwritten)
#define SM_Q    16384      // 8192  q (xq / qt / xq2)
#define SM_A    24576      // 8192  hop-tmp / a / agg / A2-T
#define SM_H    32768      // 8192  h1half / h2
#define SM_MISC 40960
#define MS_DEG   0
#define MS_DINV  64
#define MS_FOWN  128
#define MS_FPEER 192
#define MS_GOWN  256
#define MS_GPEER 320
#define MS_SCORE 384
#define MS_RED   448       // 512 floats
#define MS_PERM  960       // 64 ints
#define MS_CNT   1024      // 2048 ints (packed 2x uint16)
#define SM_TOTALF (SM_MISC + 1024 + 2048)
#define SM_BYTES  (SM_TOTALF * 4)

#define NTHR 512

__device__ __forceinline__ float leaky(float v) { return v > 0.0f ? v : NEG * v; }

// ---- packed fp32 (f32x2) ----
__device__ __forceinline__ unsigned long long packf2(float f) {
    unsigned long long d; unsigned int u = __float_as_uint(f);
    asm("mov.b64 %0, {%1, %1};" : "=l"(d) : "r"(u));
    return d;
}
__device__ __forceinline__ void fma2(unsigned long long& acc,
                                     unsigned long long a, unsigned long long b) {
    asm("fma.rn.f32x2 %0, %1, %2, %0;" : "+l"(acc) : "l"(a), "l"(b));
}
__device__ __forceinline__ unsigned long long mul2(unsigned long long a,
                                                   unsigned long long b) {
    unsigned long long o;
    asm("mul.rn.f32x2 %0, %1, %2;" : "=l"(o) : "l"(a), "l"(b));
    return o;
}
__device__ __forceinline__ void unpackf2(unsigned long long v, float& lo, float& hi) {
    unsigned int ul, uh;
    asm("mov.b64 {%0, %1}, %2;" : "=r"(ul), "=r"(uh) : "l"(v));
    lo = __uint_as_float(ul); hi = __uint_as_float(uh);
}

// ---- cluster helpers ----
__device__ __forceinline__ void cluster_sync() {
    asm volatile("barrier.cluster.arrive.aligned;" ::: "memory");
    asm volatile("barrier.cluster.wait.aligned;" ::: "memory");
}
__device__ __forceinline__ float dsread(const float* p, unsigned peer) {
    unsigned addr = (unsigned)__cvta_generic_to_shared((void*)p);
    unsigned ra; float v;
    asm volatile("mapa.shared::cluster.u32 %0, %1, %2;" : "=r"(ra) : "r"(addr), "r"(peer));
    asm volatile("ld.shared::cluster.f32 %0, [%1];" : "=f"(v) : "r"(ra));
    return v;
}

// ---- GEMM microkernel: C[64 x 128], 16 warps, tile 4 rows x 4 cols --------
// ty = t>>5 (warp id, rows 4*ty..4*ty+3 — all lanes share rows => LDS bcast);
// txc = t&31 (each warp covers all 128 cols exactly once — no dup W loads).
// W prefetched one 4-k chunk ahead in registers (R10-proven pattern).
template<int K>
__device__ __forceinline__ void gseg(const float* __restrict__ As, int ldA,
                                     const float* __restrict__ W, int wld,
                                     int ty, int txc, unsigned long long acc[4][2]) {
    const float* a0 = As + ty * 4 * ldA;
    const float* wbase = W + txc * 4;
    ulonglong2 wc[4], wn[4];
    #pragma unroll
    for (int kk = 0; kk < 4; kk++)
        wc[kk] = *(const ulonglong2*)(wbase + (size_t)kk * wld);
    #pragma unroll 2
    for (int k = 0; k < K; k += 4) {
        if (k + 4 < K) {
            #pragma unroll
            for (int kk = 0; kk < 4; kk++)
                wn[kk] = *(const ulonglong2*)(wbase + (size_t)(k + 4 + kk) * wld);
        }
        float4 av[4];
        #pragma unroll
        for (int r = 0; r < 4; r++) av[r] = *(const float4*)(a0 + r * ldA + k);
        #pragma unroll
        for (int kk = 0; kk < 4; kk++) {
            unsigned long long b0 = wc[kk].x, b1 = wc[kk].y;
            #pragma unroll
            for (int r = 0; r < 4; r++) {
                float aval = kk == 0 ? av[r].x : kk == 1 ? av[r].y : kk == 2 ? av[r].z : av[r].w;
                unsigned long long a2 = packf2(aval);
                fma2(acc[r][0], a2, b0);
                fma2(acc[r][1], a2, b1);
            }
        }
        #pragma unroll
        for (int kk = 0; kk < 4; kk++) wc[kk] = wn[kk];
    }
}

// Fused h1 microkernel: acc += a@Wf0 + q@Wf1 + (a*q)@Wf2, K=128, half cols.
// 2-k chunks; 3 W streams prefetched one chunk ahead.
__device__ __forceinline__ void gsegH1(const float* __restrict__ a,
                                       const float* __restrict__ q,
                                       const float* __restrict__ Wf, int half,
                                       int ty, int txc, unsigned long long acc[4][2]) {
    const float* a0 = a + ty * 4 * 128;
    const float* q0 = q + ty * 4 * 128;
    const float* w0 = Wf + half * 128 + txc * 4;
    ulonglong2 wa[2], wq[2], wm[2], na[2], nq[2], nm[2];
    #pragma unroll
    for (int kk = 0; kk < 2; kk++) {
        wa[kk] = *(const ulonglong2*)(w0 + (size_t)kk * 256);
        wq[kk] = *(const ulonglong2*)(w0 + (size_t)(128 + kk) * 256);
        wm[kk] = *(const ulonglong2*)(w0 + (size_t)(256 + kk) * 256);
    }
    #pragma unroll 2
    for (int k = 0; k < 128; k += 2) {
        if (k + 2 < 128) {
            #pragma unroll
            for (int kk = 0; kk < 2; kk++) {
                na[kk] = *(const ulonglong2*)(w0 + (size_t)(k + 2 + kk) * 256);
                nq[kk] = *(const ulonglong2*)(w0 + (size_t)(128 + k + 2 + kk) * 256);
                nm[kk] = *(const ulonglong2*)(w0 + (size_t)(256 + k + 2 + kk) * 256);
            }
        }
        float2 av[4], qv[4];
        #pragma unroll
        for (int r = 0; r < 4; r++) {
            av[r] = *(const float2*)(a0 + r * 128 + k);
            qv[r] = *(const float2*)(q0 + r * 128 + k);
        }
        #pragma unroll
        for (int kk = 0; kk < 2; kk++) {
            #pragma unroll
            for (int r = 0; r < 4; r++) {
                float aval = kk ? av[r].y : av[r].x;
                float qval = kk ? qv[r].y : qv[r].x;
                unsigned long long a2 = packf2(aval);
                unsigned long long q2 = packf2(qval);
                unsigned long long m2 = mul2(a2, q2);
                fma2(acc[r][0], a2, wa[kk].x); fma2(acc[r][1], a2, wa[kk].y);
                fma2(acc[r][0], q2, wq[kk].x); fma2(acc[r][1], q2, wq[kk].y);
                fma2(acc[r][0], m2, wm[kk].x); fma2(acc[r][1], m2, wm[kk].y);
            }
        }
        #pragma unroll
        for (int kk = 0; kk < 2; kk++) { wa[kk] = na[kk]; wq[kk] = nq[kk]; wm[kk] = nm[kk]; }
    }
}

// Transposed-A variant for agg: A[c][k] = S[k*64+c], tile 4 rows
__device__ __forceinline__ void gsegT(const float* __restrict__ S,
                                      const float* __restrict__ W, int wld, int K,
                                      int ty, int txc, unsigned long long acc[4][2]) {
    int c0 = ty * 4;
    const float* wbase = W + txc * 4;
    for (int k = 0; k < K; k++) {
        const ulonglong2 p0 = *(const ulonglong2*)(wbase + (size_t)k * wld);
        #pragma unroll
        for (int r = 0; r < 4; r++) {
            unsigned long long a2 = packf2(S[k * 64 + c0 + r]);
            fma2(acc[r][0], a2, p0.x);
            fma2(acc[r][1], a2, p0.y);
        }
    }
}

template<int ACT>
__device__ __forceinline__ void estore(float* C, int ldC, int ty, int txc,
                                       unsigned long long acc[4][2]) {
    #pragma unroll
    for (int r = 0; r < 4; r++) {
        float* crow = C + (ty * 4 + r) * ldC + txc * 4;
        #pragma unroll
        for (int j = 0; j < 2; j++) {
            float lo, hi; unpackf2(acc[r][j], lo, hi);
            if (ACT == 1) { lo = leaky(lo); hi = leaky(hi); }
            ((float2*)crow)[j] = make_float2(lo, hi);
        }
    }
}

// ---- in-place softmax over v[0..63] ----
__device__ void softmax64(float* v, float* red, int t) {
    if (t < 64) red[t] = v[t];
    __syncthreads();
    for (int o = 32; o; o >>= 1) { if (t < o) red[t] = fmaxf(red[t], red[t + o]); __syncthreads(); }
    float m = red[0];
    __syncthreads();
    if (t < 64) { float e = expf(v[t] - m); v[t] = e; red[t] = e; }
    __syncthreads();
    for (int o = 32; o; o >>= 1) { if (t < o) red[t] += red[t + o]; __syncthreads(); }
    float d = red[0];
    __syncthreads();
    if (t < 64) v[t] = v[t] / d;
    __syncthreads();
}

// ---- attention branch: fout = segsoftmax(leaky(MLP(kv, q))) ---------------
__device__ void attention(float* sm, int t, int ty, int txc,
                          const float* kv, const float* q,
                          int head, const float* Wk, const float* W2,
                          const float* W3, float* fout) {
    float* red = sm + SM_MISC + MS_RED;
    float* Ab  = sm + SM_A;
    float* Hb  = sm + SM_H;

    // a = kv @ Wk[head]
    {
        unsigned long long acc[4][2];
        #pragma unroll
        for (int r = 0; r < 4; r++) { acc[r][0] = 0ull; acc[r][1] = 0ull; }
        gseg<128>(kv, 128, Wk + head * 16384, 128, ty, txc, acc);
        estore<0>(Ab, 128, ty, txc, acc);
    }
    __syncthreads();

    // h2 accumulated across two h1 halves
    unsigned long long h2acc[4][2];
    #pragma unroll
    for (int r = 0; r < 4; r++) { h2acc[r][0] = 0ull; h2acc[r][1] = 0ull; }
    const float* Wf = g_wf + (size_t)head * 384 * 256;
    #pragma unroll 1
    for (int half = 0; half < 2; half++) {
        unsigned long long acc[4][2];
        #pragma unroll
        for (int r = 0; r < 4; r++) { acc[r][0] = 0ull; acc[r][1] = 0ull; }
        gsegH1(Ab, q, Wf, half, ty, txc, acc);
        estore<1>(Hb, 128, ty, txc, acc);   // h1half (leaky)
        __syncthreads();
        gseg<128>(Hb, 128, W2 + head * 32768 + half * 16384, 128, ty, txc, h2acc);
        __syncthreads();                     // protect Hb before next overwrite
    }
    estore<1>(Hb, 128, ty, txc, h2acc);      // h2 (leaky)
    __syncthreads();

    // logit = leaky(h2 @ W3[head]); segment softmax over 64. 8 partials/row.
    {
        int row = t >> 3, part = t & 7;
        const float4* hp = (const float4*)(Hb + row * 128 + part * 16);
        const float4* wp = (const float4*)(W3 + head * 128 + part * 16);
        float s = 0.0f;
        #pragma unroll
        for (int i = 0; i < 4; i++) {
            float4 a = hp[i], b = wp[i];
            s += a.x * b.x + a.y * b.y + a.z * b.z + a.w * b.w;
        }
        red[t] = s;
    }
    __syncthreads();
    if (t < 64) {
        float s = 0.0f;
        #pragma unroll
        for (int j = 0; j < 8; j++) s += red[t * 8 + j];
        fout[t] = leaky(s);
    }
    __syncthreads();
    softmax64(fout, red, t);
}

// ---------------- fold W1 ----------------
__global__ void fold_k(const float* __restrict__ W1) {
    int i = blockIdx.x * 256 + threadIdx.x;
    if (i >= 4 * 384 * 256) return;
    int w = i / (384 * 256);
    int rem = i - w * (384 * 256);
    int r = rem >> 8, c = rem & 255;
    const float* base = W1 + (size_t)w * 512 * 256;
    float v;
    if (r < 128)      v = base[r * 256 + c] + base[(r + 256) * 256 + c];
    else if (r < 256) v = base[r * 256 + c] - base[(r + 128) * 256 + c];
    else              v = base[(r + 128) * 256 + c];
    g_wf[i] = v;
}

// ---------------- THE mega kernel: one 2-CTA cluster = one batch -----------
extern __shared__ float sm[];

__global__ void __launch_bounds__(NTHR, 1) __cluster_dims__(2, 1, 1)
mega_k(const float* __restrict__ xg, const int* __restrict__ ei,
       const float* __restrict__ ew, const float* __restrict__ tx,
       const float* __restrict__ Wk, const float* __restrict__ W2,
       const float* __restrict__ W3, const float* __restrict__ lW,
       float* __restrict__ outx, float* __restrict__ outA2,
       float* __restrict__ outb, float* __restrict__ outp) {
    int t = threadIdx.x;
    int ty = t >> 5, txc = t & 31;    // warp-row tiling: warp w -> rows 4w..4w+3
    int b = blockIdx.x >> 1;
    unsigned rank = blockIdx.x & 1;

    float* Ms    = sm + SM_M;
    float* Ss    = sm + SM_S;
    float* xs    = sm + SM_X;       // x, later xc
    float* qs    = sm + SM_Q;
    float* Ab    = sm + SM_A;
    float* degs  = sm + SM_MISC + MS_DEG;
    float* dinvs = sm + SM_MISC + MS_DINV;
    float* fown  = sm + SM_MISC + MS_FOWN;
    float* fpeer = sm + SM_MISC + MS_FPEER;
    float* gown  = sm + SM_MISC + MS_GOWN;
    float* gpeer = sm + SM_MISC + MS_GPEER;
    float* sscore= sm + SM_MISC + MS_SCORE;
    float* red   = sm + SM_MISC + MS_RED;
    int*   permsh= (int*)(sm + SM_MISC + MS_PERM);
    int*   cw    = (int*)(sm + SM_MISC + MS_CNT);

    // ---- zero this CTA's A2 row-strip (26 rows x NK), overlapped ----
    {
        float4 z = make_float4(0.0f, 0.0f, 0.0f, 0.0f);
        float4* dst = (float4*)(outA2 + ((size_t)b * KK + rank * 26) * NK);
        for (int i = t; i < 26 * NK / 4; i += NTHR) dst[i] = z;
    }

    // ---- stage 0: load x, init, build deg/dinv/M/Cnt ----
    for (int i = t; i < 4096; i += NTHR) Ms[i] = 0.0f;
    for (int i = t; i < 2048; i += NTHR) cw[i] = 0;
    if (t < 64) degs[t] = 1.0f;
    for (int i = t * 4; i < 8192; i += NTHR * 4)
        *(float4*)(xs + i) = *(const float4*)(xg + (size_t)b * 8192 + i);
    __syncthreads();

    int er[4], ec[4]; float ewv[4];
    #pragma unroll
    for (int u = 0; u < 4; u++) {
        int e = b * 2048 + t + u * NTHR;
        er[u] = ei[e] - b * 64;
        ec[u] = ei[EE + e] - b * 64;
        ewv[u] = ew[e];
        atomicAdd(&degs[ec[u]], ewv[u]);
    }
    __syncthreads();
    if (t < 64) {
        float d = degs[t];
        dinvs[t] = d > 0.0f ? (1.0f / sqrtf(fmaxf(d, 1e-12f))) : 0.0f;
    }
    __syncthreads();
    #pragma unroll
    for (int u = 0; u < 4; u++) {
        atomicAdd(&Ms[ec[u] * 64 + er[u]], dinvs[er[u]] * ewv[u] * dinvs[ec[u]]);
        atomicAdd(&cw[(er[u] * 64 + ec[u]) >> 1], 1 << ((ec[u] & 1) * 16));
    }
    if (t < 64) {
        float dv = dinvs[t];
        atomicAdd(&Ms[t * 64 + t], dv * dv);
        atomicAdd(&cw[(t * 64 + t) >> 1], 1 << ((t & 1) * 16));
    }
    __syncthreads();

    // ---- stage 1: q = hop2(x) for rank0; q = broadcast target for rank1 ----
    if (rank == 0) {
        unsigned long long acc[4][2];
        #pragma unroll
        for (int r = 0; r < 4; r++) { acc[r][0] = 0ull; acc[r][1] = 0ull; }
        gseg<64>(Ms, 64, xs, 128, ty, txc, acc);
        estore<0>(Ab, 128, ty, txc, acc);
        __syncthreads();
        unsigned long long acc2[4][2];
        #pragma unroll
        for (int r = 0; r < 4; r++) { acc2[r][0] = 0ull; acc2[r][1] = 0ull; }
        gseg<64>(Ms, 64, Ab, 128, ty, txc, acc2);
        estore<0>(qs, 128, ty, txc, acc2);
    } else {
        for (int i = t * 4; i < 8192; i += NTHR * 4)
            *(float4*)(qs + i) = *(const float4*)(tx + b * 128 + (i & 127));
    }
    __syncthreads();

    // ---- stage 2: attention #1 (head = rank) -> fown ----
    attention(sm, t, ty, txc, xs, qs, (int)rank, Wk, W2, W3, fown);

    cluster_sync();
    if (t < 64) fpeer[t] = dsread(fown + t, rank ^ 1);
    __syncthreads();

    // ---- stage 3: build S (edge softmax, count-weighted), 8 partials/col ----
    {
        const float* f1 = rank ? fpeer : fown;
        const float* f2 = rank ? fown : fpeer;
        int c = t >> 3, rq = t & 7;
        float f1c = f1[c];
        float mx = -3.0e38f;
        for (int r = rq * 8; r < rq * 8 + 8; r++) {
            int cnt = (cw[(r * 64 + c) >> 1] >> ((c & 1) * 16)) & 0xffff;
            if (cnt) mx = fmaxf(mx, leaky(f1c + f2[r]));
        }
        red[t] = mx; __syncthreads();
        mx = red[c * 8];
        #pragma unroll
        for (int j = 1; j < 8; j++) mx = fmaxf(mx, red[c * 8 + j]);
        __syncthreads();
        float dp = 0.0f;
        for (int r = rq * 8; r < rq * 8 + 8; r++) {
            int cnt = (cw[(r * 64 + c) >> 1] >> ((c & 1) * 16)) & 0xffff;
            float e = 0.0f;
            if (cnt) e = (float)cnt * expf(leaky(f1c + f2[r]) - mx);
            Ss[r * 64 + c] = e; dp += e;
        }
        red[t] = dp; __syncthreads();
        float sum = red[c * 8];
        #pragma unroll
        for (int j = 1; j < 8; j++) sum += red[c * 8 + j];
        float inv = 1.0f / sum;
        for (int r = rq * 8; r < rq * 8 + 8; r++) Ss[r * 64 + c] *= inv;
        __syncthreads();
    }

    // ---- stage 4: agg = S^T x -> Ab ; xc = mean_h leaky(x + agg @ lW[h]) ----
    {
        unsigned long long acc[4][2];
        #pragma unroll
        for (int r = 0; r < 4; r++) { acc[r][0] = 0ull; acc[r][1] = 0ull; }
        gsegT(Ss, xs, 128, 64, ty, txc, acc);
        estore<0>(Ab, 128, ty, txc, acc);
    }
    __syncthreads();
    {
        unsigned long long a0[4][2], a1[4][2];
        #pragma unroll
        for (int r = 0; r < 4; r++) { a0[r][0]=0ull;a0[r][1]=0ull;a1[r][0]=0ull;a1[r][1]=0ull; }
        gseg<128>(Ab, 128, lW,         128, ty, txc, a0);
        gseg<128>(Ab, 128, lW + 16384, 128, ty, txc, a1);
        #pragma unroll
        for (int r = 0; r < 4; r++) {
            int row = ty * 4 + r;
            #pragma unroll
            for (int j = 0; j < 2; j++) {
                float l0, h0, l1, h1v;
                unpackf2(a0[r][j], l0, h0);
                unpackf2(a1[r][j], l1, h1v);
                int col = txc * 4 + 2 * j;
                float x0 = xs[row * 128 + col], x1 = xs[row * 128 + col + 1];
                float vlo = 0.5f * (leaky(x0 + l0) + leaky(x0 + l1));
                float vhi = 0.5f * (leaky(x1 + h0) + leaky(x1 + h1v));
                *(float2*)(xs + row * 128 + col) = make_float2(vlo, vhi);  // x -> xc in place
            }
        }
    }
    __syncthreads();

    // ---- stage 5: q2 = hop2(xc) for rank0 (rank1 keeps qt in qs) ----
    if (rank == 0) {
        unsigned long long acc[4][2];
        #pragma unroll
        for (int r = 0; r < 4; r++) { acc[r][0] = 0ull; acc[r][1] = 0ull; }
        gseg<64>(Ms, 64, xs, 128, ty, txc, acc);
        estore<0>(Ab, 128, ty, txc, acc);
        __syncthreads();
        unsigned long long acc2[4][2];
        #pragma unroll
        for (int r = 0; r < 4; r++) { acc2[r][0] = 0ull; acc2[r][1] = 0ull; }
        gseg<64>(Ms, 64, Ab, 128, ty, txc, acc2);
        estore<0>(qs, 128, ty, txc, acc2);
        __syncthreads();
    }

    // ---- stage 6: attention #2 (head = 2 + rank), kv = xc -> gown ----
    attention(sm, t, ty, txc, xs, qs, 2 + (int)rank, Wk, W2, W3, gown);

    cluster_sync();
    if (t < 64) gpeer[t] = dsread(gown + t, rank ^ 1);
    __syncthreads();

    // ---- stage 7: cluster score softmax + top-52 ----
    if (t < 64) sscore[t] = gown[t] + gpeer[t];
    __syncthreads();
    softmax64(sscore, red, t);
    if (t < 32) {
        float v0 = sscore[t], v1 = sscore[t + 32];
        for (int j = 0; j < KK; j++) {
            float mv = v0; int mi = t;
            if (v1 > mv) { mv = v1; mi = t + 32; }
            #pragma unroll
            for (int off = 16; off; off >>= 1) {
                float ov = __shfl_xor_sync(0xffffffffu, mv, off);
                int   oi = __shfl_xor_sync(0xffffffffu, mi, off);
                if (ov > mv || (ov == mv && oi < mi)) { mv = ov; mi = oi; }
            }
            if (t == 0) permsh[j] = mi;
            if (mi < 32) { if (t == mi) v0 = -3.0e38f; }
            else         { if (t == mi - 32) v1 = -3.0e38f; }
        }
    }
    __syncthreads();

    // ---- stage 8: outputs ----
    if (rank == 0) {
        // x_out: re-read x from global (xs now holds xc)
        for (int i = t; i < KK * 32; i += NTHR) {
            int e = i >> 5, c4 = (i & 31) * 4;
            int p = permsh[e];
            float sc = sscore[p];
            float4 xv = *(const float4*)(xg + (size_t)b * 8192 + p * 128 + c4);
            *(float4*)(outx + (size_t)(b * KK + e) * 128 + c4) =
                make_float4(xv.x * sc, xv.y * sc, xv.z * sc, xv.w * sc);
        }
        if (t < KK) {
            int p = permsh[t];
            outb[b * KK + t] = (float)b;
            outp[b * KK + t] = (float)(b * 64 + p);
        }
    }

    // A2 block: T = A_d @ S_sel (in Ab); A2 rows split by rank
    float* T = Ab;   // 64*52 floats
    __syncthreads();
    for (int i = t; i < 64 * KK; i += NTHR) {
        int r = i / KK, j = i - r * KK;
        int cj = permsh[j];
        float acc = 0.0f;
        #pragma unroll
        for (int c = 0; c < 64; c++) acc += Ms[c * 64 + r] * Ss[c * 64 + cj];
        T[i] = acc;
    }
    __syncthreads();
    for (int o = t; o < 26 * KK; o += NTHR) {
        int il = o / KK, j = o - il * KK;
        int i = (int)rank * 26 + il;
        float v;
        if (i == j) v = 1.0f;
        else {
            int ci = permsh[i];
            v = 0.0f;
            #pragma unroll
            for (int r = 0; r < 64; r++) v += Ss[r * 64 + ci] * T[r * KK + j];
        }
        outA2[(size_t)(b * KK + i) * NK + (size_t)(b * KK + j)] = v;
    }
}

// =======================================================================
extern "C" void kernel_launch(void* const* d_in, const int* in_sizes, int n_in,
                              void* d_out, int out_size) {
    const float* x   = (const float*)d_in[0];
    const int*   ei  = (const int*)d_in[1];
    const float* ewt = (const float*)d_in[2];
    const float* tx  = (const float*)d_in[3];
    const float* Wk  = (const float*)d_in[5];
    const float* W1  = (const float*)d_in[6];
    const float* W2  = (const float*)d_in[7];
    const float* W3  = (const float*)d_in[8];
    const float* lW  = (const float*)d_in[9];
    float* out = (float*)d_out;

    float* out_x    = out;
    float* out_A2   = out + (size_t)NK * HH;
    float* out_bat  = out + (size_t)NK * HH + (size_t)NK * NK;
    float* out_perm = out_bat + NK;

    cudaFuncSetAttribute(mega_k, cudaFuncAttributeMaxDynamicSharedMemorySize, SM_BYTES);

    fold_k<<<(4 * 384 * 256 + 255) / 256, 256>>>(W1);
    mega_k<<<2 * BB, NTHR, SM_BYTES>>>(x, ei, ewt, tx, Wk, W2, W3, lW,
                                       out_x, out_A2, out_bat, out_perm);
}

// round 15
// speedup vs baseline: 1.2772x; 1.0118x over previous
#include <cuda_runtime.h>
#include <cstdint>
#include <math.h>

#define BB   64
#define HH   128
#define NT   4096
#define EE   131072
#define KK   52
#define NK   3328
#define NEG  0.01f

// Global scratch: folded W1 (4 heads x 384 x 256):
// rows 0..127 = W1_0+W1_2, 128..255 = W1_1-W1_2, 256..383 = W1_3
__device__ float g_wf[4*384*256];

// ---------------- shared memory layout (float offsets) — ~172 KB ----------
#define SM_M    0          // 4096  M[c*64+r] = A_d[r][c]
#define SM_S    4096       // 4096  S[r*64+c]
#define SM_X    8192       // 8192  x -> xc (overwritten)
#define SM_Q    16384      // 8192  q (xq / qt / xq2)
#define SM_A    24576      // 8192  hop-tmp / a / agg / A2-T
#define SM_H    32768      // 8192  h1half / h2
#define SM_MISC 40960
#define MS_DEG   0
#define MS_DINV  64
#define MS_FOWN  128
#define MS_FPEER 192
#define MS_GOWN  256
#define MS_GPEER 320
#define MS_SCORE 384
#define MS_RED   448       // 512 floats
#define MS_PERM  960       // 64 ints
#define MS_CNT   1024      // 2048 ints (packed 2x uint16)
#define SM_TOTALF (SM_MISC + 1024 + 2048)
#define SM_BYTES  (SM_TOTALF * 4)

#define NTHR 512

__device__ __forceinline__ float leaky(float v) { return v > 0.0f ? v : NEG * v; }

// ---- packed fp32 (f32x2) ----
__device__ __forceinline__ unsigned long long packf2(float f) {
    unsigned long long d; unsigned int u = __float_as_uint(f);
    asm("mov.b64 %0, {%1, %1};" : "=l"(d) : "r"(u));
    return d;
}
__device__ __forceinline__ void fma2(unsigned long long& acc,
                                     unsigned long long a, unsigned long long b) {
    asm("fma.rn.f32x2 %0, %1, %2, %0;" : "+l"(acc) : "l"(a), "l"(b));
}
__device__ __forceinline__ unsigned long long mul2(unsigned long long a,
                                                   unsigned long long b) {
    unsigned long long o;
    asm("mul.rn.f32x2 %0, %1, %2;" : "=l"(o) : "l"(a), "l"(b));
    return o;
}
__device__ __forceinline__ void unpackf2(unsigned long long v, float& lo, float& hi) {
    unsigned int ul, uh;
    asm("mov.b64 {%0, %1}, %2;" : "=r"(ul), "=r"(uh) : "l"(v));
    lo = __uint_as_float(ul); hi = __uint_as_float(uh);
}

// ---- cluster helpers ----
__device__ __forceinline__ void cluster_sync() {
    asm volatile("barrier.cluster.arrive.aligned;" ::: "memory");
    asm volatile("barrier.cluster.wait.aligned;" ::: "memory");
}
__device__ __forceinline__ float dsread(const float* p, unsigned peer) {
    unsigned addr = (unsigned)__cvta_generic_to_shared((void*)p);
    unsigned ra; float v;
    asm volatile("mapa.shared::cluster.u32 %0, %1, %2;" : "=r"(ra) : "r"(addr), "r"(peer));
    asm volatile("ld.shared::cluster.f32 %0, [%1];" : "=f"(v) : "r"(ra));
    return v;
}

// ---- GEMM microkernel: C[64 x 128], 16 warps, tile 4 rows x 4 cols --------
// ty = t>>5 (warp id, rows 4*ty..4*ty+3 — all lanes share rows => LDS bcast);
// txc = t&31 (each warp covers all 128 cols exactly once — no dup W loads).
// W prefetched one 4-k chunk ahead in registers.
template<int K>
__device__ __forceinline__ void gseg(const float* __restrict__ As, int ldA,
                                     const float* __restrict__ W, int wld,
                                     int ty, int txc, unsigned long long acc[4][2]) {
    const float* a0 = As + ty * 4 * ldA;
    const float* wbase = W + txc * 4;
    ulonglong2 wc[4], wn[4];
    #pragma unroll
    for (int kk = 0; kk < 4; kk++)
        wc[kk] = *(const ulonglong2*)(wbase + (size_t)kk * wld);
    #pragma unroll 2
    for (int k = 0; k < K; k += 4) {
        if (k + 4 < K) {
            #pragma unroll
            for (int kk = 0; kk < 4; kk++)
                wn[kk] = *(const ulonglong2*)(wbase + (size_t)(k + 4 + kk) * wld);
        }
        float4 av[4];
        #pragma unroll
        for (int r = 0; r < 4; r++) av[r] = *(const float4*)(a0 + r * ldA + k);
        #pragma unroll
        for (int kk = 0; kk < 4; kk++) {
            unsigned long long b0 = wc[kk].x, b1 = wc[kk].y;
            #pragma unroll
            for (int r = 0; r < 4; r++) {
                float aval = kk == 0 ? av[r].x : kk == 1 ? av[r].y : kk == 2 ? av[r].z : av[r].w;
                unsigned long long a2 = packf2(aval);
                fma2(acc[r][0], a2, b0);
                fma2(acc[r][1], a2, b1);
            }
        }
        #pragma unroll
        for (int kk = 0; kk < 4; kk++) wc[kk] = wn[kk];
    }
}

// Fused h1 microkernel: acc += a@Wf0 + q@Wf1 + (a*q)@Wf2, K=128, half cols.
// 2-k chunks; 3 W streams prefetched one chunk ahead.
__device__ __forceinline__ void gsegH1(const float* __restrict__ a,
                                       const float* __restrict__ q,
                                       const float* __restrict__ Wf, int half,
                                       int ty, int txc, unsigned long long acc[4][2]) {
    const float* a0 = a + ty * 4 * 128;
    const float* q0 = q + ty * 4 * 128;
    const float* w0 = Wf + half * 128 + txc * 4;
    ulonglong2 wa[2], wq[2], wm[2], na[2], nq[2], nm[2];
    #pragma unroll
    for (int kk = 0; kk < 2; kk++) {
        wa[kk] = *(const ulonglong2*)(w0 + (size_t)kk * 256);
        wq[kk] = *(const ulonglong2*)(w0 + (size_t)(128 + kk) * 256);
        wm[kk] = *(const ulonglong2*)(w0 + (size_t)(256 + kk) * 256);
    }
    #pragma unroll 2
    for (int k = 0; k < 128; k += 2) {
        if (k + 2 < 128) {
            #pragma unroll
            for (int kk = 0; kk < 2; kk++) {
                na[kk] = *(const ulonglong2*)(w0 + (size_t)(k + 2 + kk) * 256);
                nq[kk] = *(const ulonglong2*)(w0 + (size_t)(128 + k + 2 + kk) * 256);
                nm[kk] = *(const ulonglong2*)(w0 + (size_t)(256 + k + 2 + kk) * 256);
            }
        }
        float2 av[4], qv[4];
        #pragma unroll
        for (int r = 0; r < 4; r++) {
            av[r] = *(const float2*)(a0 + r * 128 + k);
            qv[r] = *(const float2*)(q0 + r * 128 + k);
        }
        #pragma unroll
        for (int kk = 0; kk < 2; kk++) {
            #pragma unroll
            for (int r = 0; r < 4; r++) {
                float aval = kk ? av[r].y : av[r].x;
                float qval = kk ? qv[r].y : qv[r].x;
                unsigned long long a2 = packf2(aval);
                unsigned long long q2 = packf2(qval);
                unsigned long long m2 = mul2(a2, q2);
                fma2(acc[r][0], a2, wa[kk].x); fma2(acc[r][1], a2, wa[kk].y);
                fma2(acc[r][0], q2, wq[kk].x); fma2(acc[r][1], q2, wq[kk].y);
                fma2(acc[r][0], m2, wm[kk].x); fma2(acc[r][1], m2, wm[kk].y);
            }
        }
        #pragma unroll
        for (int kk = 0; kk < 2; kk++) { wa[kk] = na[kk]; wq[kk] = nq[kk]; wm[kk] = nm[kk]; }
    }
}

// Transposed-A variant for agg: A[c][k] = S[k*64+c], tile 4 rows
__device__ __forceinline__ void gsegT(const float* __restrict__ S,
                                      const float* __restrict__ W, int wld, int K,
                                      int ty, int txc, unsigned long long acc[4][2]) {
    int c0 = ty * 4;
    const float* wbase = W + txc * 4;
    for (int k = 0; k < K; k++) {
        const ulonglong2 p0 = *(const ulonglong2*)(wbase + (size_t)k * wld);
        #pragma unroll
        for (int r = 0; r < 4; r++) {
            unsigned long long a2 = packf2(S[k * 64 + c0 + r]);
            fma2(acc[r][0], a2, p0.x);
            fma2(acc[r][1], a2, p0.y);
        }
    }
}

template<int ACT>
__device__ __forceinline__ void estore(float* C, int ldC, int ty, int txc,
                                       unsigned long long acc[4][2]) {
    #pragma unroll
    for (int r = 0; r < 4; r++) {
        float* crow = C + (ty * 4 + r) * ldC + txc * 4;
        #pragma unroll
        for (int j = 0; j < 2; j++) {
            float lo, hi; unpackf2(acc[r][j], lo, hi);
            if (ACT == 1) { lo = leaky(lo); hi = leaky(hi); }
            ((float2*)crow)[j] = make_float2(lo, hi);
        }
    }
}

// ---- in-place softmax over v[0..63] ----
__device__ void softmax64(float* v, float* red, int t) {
    if (t < 64) red[t] = v[t];
    __syncthreads();
    for (int o = 32; o; o >>= 1) { if (t < o) red[t] = fmaxf(red[t], red[t + o]); __syncthreads(); }
    float m = red[0];
    __syncthreads();
    if (t < 64) { float e = expf(v[t] - m); v[t] = e; red[t] = e; }
    __syncthreads();
    for (int o = 32; o; o >>= 1) { if (t < o) red[t] += red[t + o]; __syncthreads(); }
    float d = red[0];
    __syncthreads();
    if (t < 64) v[t] = v[t] / d;
    __syncthreads();
}

// ---- attention branch: fout = segsoftmax(leaky(MLP(kv, q))) ---------------
// KEY: a -> h1 -> h2 smem traffic is warp-row-private (warp ty produces and
// consumes rows 4ty..4ty+3; cross-thread operands are global weights), so the
// whole MLP chain needs only __syncwarp() until the cross-warp logit stage.
__device__ void attention(float* sm, int t, int ty, int txc,
                          const float* kv, const float* q,
                          int head, const float* Wk, const float* W2,
                          const float* W3, float* fout) {
    float* red = sm + SM_MISC + MS_RED;
    float* Ab  = sm + SM_A;
    float* Hb  = sm + SM_H;

    // a = kv @ Wk[head]
    {
        unsigned long long acc[4][2];
        #pragma unroll
        for (int r = 0; r < 4; r++) { acc[r][0] = 0ull; acc[r][1] = 0ull; }
        gseg<128>(kv, 128, Wk + head * 16384, 128, ty, txc, acc);
        estore<0>(Ab, 128, ty, txc, acc);
    }
    __syncwarp();

    // h2 accumulated across two h1 halves — warp-private rows throughout
    unsigned long long h2acc[4][2];
    #pragma unroll
    for (int r = 0; r < 4; r++) { h2acc[r][0] = 0ull; h2acc[r][1] = 0ull; }
    const float* Wf = g_wf + (size_t)head * 384 * 256;
    #pragma unroll 1
    for (int half = 0; half < 2; half++) {
        unsigned long long acc[4][2];
        #pragma unroll
        for (int r = 0; r < 4; r++) { acc[r][0] = 0ull; acc[r][1] = 0ull; }
        gsegH1(Ab, q, Wf, half, ty, txc, acc);
        estore<1>(Hb, 128, ty, txc, acc);   // h1half (leaky)
        __syncwarp();
        gseg<128>(Hb, 128, W2 + head * 32768 + half * 16384, 128, ty, txc, h2acc);
        __syncwarp();                        // own-rows Hb reuse next iteration
    }
    estore<1>(Hb, 128, ty, txc, h2acc);      // h2 (leaky)
    __syncthreads();                         // logit reads Hb cross-warp

    // logit = leaky(h2 @ W3[head]); segment softmax over 64. 8 partials/row.
    {
        int row = t >> 3, part = t & 7;
        const float4* hp = (const float4*)(Hb + row * 128 + part * 16);
        const float4* wp = (const float4*)(W3 + head * 128 + part * 16);
        float s = 0.0f;
        #pragma unroll
        for (int i = 0; i < 4; i++) {
            float4 a = hp[i], b = wp[i];
            s += a.x * b.x + a.y * b.y + a.z * b.z + a.w * b.w;
        }
        red[t] = s;
    }
    __syncthreads();
    if (t < 64) {
        float s = 0.0f;
        #pragma unroll
        for (int j = 0; j < 8; j++) s += red[t * 8 + j];
        fout[t] = leaky(s);
    }
    __syncthreads();
    softmax64(fout, red, t);
}

// ---------------- fold W1 ----------------
__global__ void fold_k(const float* __restrict__ W1) {
    int i = blockIdx.x * 256 + threadIdx.x;
    if (i >= 4 * 384 * 256) return;
    int w = i / (384 * 256);
    int rem = i - w * (384 * 256);
    int r = rem >> 8, c = rem & 255;
    const float* base = W1 + (size_t)w * 512 * 256;
    float v;
    if (r < 128)      v = base[r * 256 + c] + base[(r + 256) * 256 + c];
    else if (r < 256) v = base[r * 256 + c] - base[(r + 128) * 256 + c];
    else              v = base[(r + 128) * 256 + c];
    g_wf[i] = v;
}

// ---------------- THE mega kernel: one 2-CTA cluster = one batch -----------
extern __shared__ float sm[];

__global__ void __launch_bounds__(NTHR, 1) __cluster_dims__(2, 1, 1)
mega_k(const float* __restrict__ xg, const int* __restrict__ ei,
       const float* __restrict__ ew, const float* __restrict__ tx,
       const float* __restrict__ Wk, const float* __restrict__ W2,
       const float* __restrict__ W3, const float* __restrict__ lW,
       float* __restrict__ outx, float* __restrict__ outA2,
       float* __restrict__ outb, float* __restrict__ outp) {
    int t = threadIdx.x;
    int ty = t >> 5, txc = t & 31;    // warp-row tiling: warp w -> rows 4w..4w+3
    int b = blockIdx.x >> 1;
    unsigned rank = blockIdx.x & 1;

    float* Ms    = sm + SM_M;
    float* Ss    = sm + SM_S;
    float* xs    = sm + SM_X;       // x, later xc
    float* qs    = sm + SM_Q;
    float* Ab    = sm + SM_A;
    float* degs  = sm + SM_MISC + MS_DEG;
    float* dinvs = sm + SM_MISC + MS_DINV;
    float* fown  = sm + SM_MISC + MS_FOWN;
    float* fpeer = sm + SM_MISC + MS_FPEER;
    float* gown  = sm + SM_MISC + MS_GOWN;
    float* gpeer = sm + SM_MISC + MS_GPEER;
    float* sscore= sm + SM_MISC + MS_SCORE;
    float* red   = sm + SM_MISC + MS_RED;
    int*   permsh= (int*)(sm + SM_MISC + MS_PERM);
    int*   cw    = (int*)(sm + SM_MISC + MS_CNT);

    // ---- zero this CTA's A2 row-strip (26 rows x NK), overlapped ----
    {
        float4 z = make_float4(0.0f, 0.0f, 0.0f, 0.0f);
        float4* dst = (float4*)(outA2 + ((size_t)b * KK + rank * 26) * NK);
        for (int i = t; i < 26 * NK / 4; i += NTHR) dst[i] = z;
    }

    // ---- stage 0: load x, init, build deg/dinv/M/Cnt ----
    for (int i = t; i < 4096; i += NTHR) Ms[i] = 0.0f;
    for (int i = t; i < 2048; i += NTHR) cw[i] = 0;
    if (t < 64) degs[t] = 1.0f;
    for (int i = t * 4; i < 8192; i += NTHR * 4)
        *(float4*)(xs + i) = *(const float4*)(xg + (size_t)b * 8192 + i);
    __syncthreads();

    int er[4], ec[4]; float ewv[4];
    #pragma unroll
    for (int u = 0; u < 4; u++) {
        int e = b * 2048 + t + u * NTHR;
        er[u] = ei[e] - b * 64;
        ec[u] = ei[EE + e] - b * 64;
        ewv[u] = ew[e];
        atomicAdd(&degs[ec[u]], ewv[u]);
    }
    __syncthreads();
    if (t < 64) {
        float d = degs[t];
        dinvs[t] = d > 0.0f ? (1.0f / sqrtf(fmaxf(d, 1e-12f))) : 0.0f;
    }
    __syncthreads();
    #pragma unroll
    for (int u = 0; u < 4; u++) {
        atomicAdd(&Ms[ec[u] * 64 + er[u]], dinvs[er[u]] * ewv[u] * dinvs[ec[u]]);
        atomicAdd(&cw[(er[u] * 64 + ec[u]) >> 1], 1 << ((ec[u] & 1) * 16));
    }
    if (t < 64) {
        float dv = dinvs[t];
        atomicAdd(&Ms[t * 64 + t], dv * dv);
        atomicAdd(&cw[(t * 64 + t) >> 1], 1 << ((t & 1) * 16));
    }
    __syncthreads();

    // ---- stage 1: q = hop2(x) for rank0; q = broadcast target for rank1 ----
    if (rank == 0) {
        unsigned long long acc[4][2];
        #pragma unroll
        for (int r = 0; r < 4; r++) { acc[r][0] = 0ull; acc[r][1] = 0ull; }
        gseg<64>(Ms, 64, xs, 128, ty, txc, acc);
        estore<0>(Ab, 128, ty, txc, acc);
        __syncthreads();                      // Ab read cross-warp below
        unsigned long long acc2[4][2];
        #pragma unroll
        for (int r = 0; r < 4; r++) { acc2[r][0] = 0ull; acc2[r][1] = 0ull; }
        gseg<64>(Ms, 64, Ab, 128, ty, txc, acc2);
        estore<0>(qs, 128, ty, txc, acc2);
    } else {
        for (int i = t * 4; i < 8192; i += NTHR * 4)
            *(float4*)(qs + i) = *(const float4*)(tx + b * 128 + (i & 127));
    }
    __syncthreads();

    // ---- stage 2: attention #1 (head = rank) -> fown ----
    attention(sm, t, ty, txc, xs, qs, (int)rank, Wk, W2, W3, fown);

    cluster_sync();
    if (t < 64) fpeer[t] = dsread(fown + t, rank ^ 1);
    __syncthreads();

    // ---- stage 3: build S (edge softmax, count-weighted), 8 partials/col ----
    {
        const float* f1 = rank ? fpeer : fown;
        const float* f2 = rank ? fown : fpeer;
        int c = t >> 3, rq = t & 7;
        float f1c = f1[c];
        float mx = -3.0e38f;
        for (int r = rq * 8; r < rq * 8 + 8; r++) {
            int cnt = (cw[(r * 64 + c) >> 1] >> ((c & 1) * 16)) & 0xffff;
            if (cnt) mx = fmaxf(mx, leaky(f1c + f2[r]));
        }
        red[t] = mx; __syncthreads();
        mx = red[c * 8];
        #pragma unroll
        for (int j = 1; j < 8; j++) mx = fmaxf(mx, red[c * 8 + j]);
        __syncthreads();
        float dp = 0.0f;
        for (int r = rq * 8; r < rq * 8 + 8; r++) {
            int cnt = (cw[(r * 64 + c) >> 1] >> ((c & 1) * 16)) & 0xffff;
            float e = 0.0f;
            if (cnt) e = (float)cnt * expf(leaky(f1c + f2[r]) - mx);
            Ss[r * 64 + c] = e; dp += e;
        }
        red[t] = dp; __syncthreads();
        float sum = red[c * 8];
        #pragma unroll
        for (int j = 1; j < 8; j++) sum += red[c * 8 + j];
        float inv = 1.0f / sum;
        for (int r = rq * 8; r < rq * 8 + 8; r++) Ss[r * 64 + c] *= inv;
        __syncthreads();
    }

    // ---- stage 4: agg = S^T x -> Ab ; xc = mean_h leaky(x + agg @ lW[h]) ----
    {
        unsigned long long acc[4][2];
        #pragma unroll
        for (int r = 0; r < 4; r++) { acc[r][0] = 0ull; acc[r][1] = 0ull; }
        gsegT(Ss, xs, 128, 64, ty, txc, acc);
        estore<0>(Ab, 128, ty, txc, acc);
    }
    __syncwarp();                             // Ab rows are warp-private below
    {
        unsigned long long a0[4][2], a1[4][2];
        #pragma unroll
        for (int r = 0; r < 4; r++) { a0[r][0]=0ull;a0[r][1]=0ull;a1[r][0]=0ull;a1[r][1]=0ull; }
        gseg<128>(Ab, 128, lW,         128, ty, txc, a0);
        gseg<128>(Ab, 128, lW + 16384, 128, ty, txc, a1);
        #pragma unroll
        for (int r = 0; r < 4; r++) {
            int row = ty * 4 + r;
            #pragma unroll
            for (int j = 0; j < 2; j++) {
                float l0, h0, l1, h1v;
                unpackf2(a0[r][j], l0, h0);
                unpackf2(a1[r][j], l1, h1v);
                int col = txc * 4 + 2 * j;
                float x0 = xs[row * 128 + col], x1 = xs[row * 128 + col + 1];
                float vlo = 0.5f * (leaky(x0 + l0) + leaky(x0 + l1));
                float vhi = 0.5f * (leaky(x1 + h0) + leaky(x1 + h1v));
                *(float2*)(xs + row * 128 + col) = make_float2(vlo, vhi);  // x -> xc in place
            }
        }
    }
    __syncthreads();

    // ---- stage 5: q2 = hop2(xc) for rank0 (rank1 keeps qt in qs) ----
    if (rank == 0) {
        unsigned long long acc[4][2];
        #pragma unroll
        for (int r = 0; r < 4; r++) { acc[r][0] = 0ull; acc[r][1] = 0ull; }
        gseg<64>(Ms, 64, xs, 128, ty, txc, acc);
        estore<0>(Ab, 128, ty, txc, acc);
        __syncthreads();
        unsigned long long acc2[4][2];
        #pragma unroll
        for (int r = 0; r < 4; r++) { acc2[r][0] = 0ull; acc2[r][1] = 0ull; }
        gseg<64>(Ms, 64, Ab, 128, ty, txc, acc2);
        estore<0>(qs, 128, ty, txc, acc2);
        __syncthreads();
    }

    // ---- stage 6: attention #2 (head = 2 + rank), kv = xc -> gown ----
    attention(sm, t, ty, txc, xs, qs, 2 + (int)rank, Wk, W2, W3, gown);

    cluster_sync();
    if (t < 64) gpeer[t] = dsread(gown + t, rank ^ 1);
    __syncthreads();

    // ---- stage 7: cluster score softmax + top-52 ----
    if (t < 64) sscore[t] = gown[t] + gpeer[t];
    __syncthreads();
    softmax64(sscore, red, t);
    if (t < 32) {
        float v0 = sscore[t], v1 = sscore[t + 32];
        for (int j = 0; j < KK; j++) {
            float mv = v0; int mi = t;
            if (v1 > mv) { mv = v1; mi = t + 32; }
            #pragma unroll
            for (int off = 16; off; off >>= 1) {
                float ov = __shfl_xor_sync(0xffffffffu, mv, off);
                int   oi = __shfl_xor_sync(0xffffffffu, mi, off);
                if (ov > mv || (ov == mv && oi < mi)) { mv = ov; mi = oi; }
            }
            if (t == 0) permsh[j] = mi;
            if (mi < 32) { if (t == mi) v0 = -3.0e38f; }
            else         { if (t == mi - 32) v1 = -3.0e38f; }
        }
    }
    __syncthreads();

    // ---- stage 8: outputs ----
    if (rank == 0) {
        // x_out: re-read x from global (xs now holds xc)
        for (int i = t; i < KK * 32; i += NTHR) {
            int e = i >> 5, c4 = (i & 31) * 4;
            int p = permsh[e];
            float sc = sscore[p];
            float4 xv = *(const float4*)(xg + (size_t)b * 8192 + p * 128 + c4);
            *(float4*)(outx + (size_t)(b * KK + e) * 128 + c4) =
                make_float4(xv.x * sc, xv.y * sc, xv.z * sc, xv.w * sc);
        }
        if (t < KK) {
            int p = permsh[t];
            outb[b * KK + t] = (float)b;
            outp[b * KK + t] = (float)(b * 64 + p);
        }
    }

    // A2 block: T = A_d @ S_sel (in Ab); A2 rows split by rank
    float* T = Ab;   // 64*52 floats
    __syncthreads();
    for (int i = t; i < 64 * KK; i += NTHR) {
        int r = i / KK, j = i - r * KK;
        int cj = permsh[j];
        float acc = 0.0f;
        #pragma unroll
        for (int c = 0; c < 64; c++) acc += Ms[c * 64 + r] * Ss[c * 64 + cj];
        T[i] = acc;
    }
    __syncthreads();
    for (int o = t; o < 26 * KK; o += NTHR) {
        int il = o / KK, j = o - il * KK;
        int i = (int)rank * 26 + il;
        float v;
        if (i == j) v = 1.0f;
        else {
            int ci = permsh[i];
            v = 0.0f;
            #pragma unroll
            for (int r = 0; r < 64; r++) v += Ss[r * 64 + ci] * T[r * KK + j];
        }
        outA2[(size_t)(b * KK + i) * NK + (size_t)(b * KK + j)] = v;
    }
}

// =======================================================================
extern "C" void kernel_launch(void* const* d_in, const int* in_sizes, int n_in,
                              void* d_out, int out_size) {
    const float* x   = (const float*)d_in[0];
    const int*   ei  = (const int*)d_in[1];
    const float* ewt = (const float*)d_in[2];
    const float* tx  = (const float*)d_in[3];
    const float* Wk  = (const float*)d_in[5];
    const float* W1  = (const float*)d_in[6];
    const float* W2  = (const float*)d_in[7];
    const float* W3  = (const float*)d_in[8];
    const float* lW  = (const float*)d_in[9];
    float* out = (float*)d_out;

    float* out_x    = out;
    float* out_A2   = out + (size_t)NK * HH;
    float* out_bat  = out + (size_t)NK * HH + (size_t)NK * NK;
    float* out_perm = out_bat + NK;

    cudaFuncSetAttribute(mega_k, cudaFuncAttributeMaxDynamicSharedMemorySize, SM_BYTES);

    fold_k<<<(4 * 384 * 256 + 255) / 256, 256>>>(W1);
    mega_k<<<2 * BB, NTHR, SM_BYTES>>>(x, ei, ewt, tx, Wk, W2, W3, lW,
                                       out_x, out_A2, out_bat, out_perm);
}